// round 2
// baseline (speedup 1.0000x reference)
#include <cuda_runtime.h>
#include <cstdint>

// Problem constants
#define NXC 64          // nx grid cells
#define NYC 64          // ny grid cells
#define SCALE 16
#define PP 15           // scale-1
#define BB 4
#define CC 3
#define HH 1024
#define WW 1024
#define NNODES 4096     // 64*64
static const long long A_ELEMS   = (long long)BB * NNODES * NNODES;  // 67108864
static const long long DATA_ELEMS = (long long)BB * CC * HH * WW;    // 12582912

// ---------------------------------------------------------------------------
// Kernel 1: zero-fill A region of d_out and copy data into the tail.
// Pure float4 streaming writes; grid-stride.
// ---------------------------------------------------------------------------
__global__ void fill_kernel(const float4* __restrict__ src,
                            float4* __restrict__ out,
                            long long a4, long long total4) {
    long long i = (long long)blockIdx.x * blockDim.x + threadIdx.x;
    long long stride = (long long)gridDim.x * blockDim.x;
    const float4 z = make_float4(0.f, 0.f, 0.f, 0.f);
    for (; i < total4; i += stride) {
        if (i < a4) {
            out[i] = z;
        } else {
            out[i] = src[i - a4];
        }
    }
}

// ---------------------------------------------------------------------------
// Kernel 2: one warp per adjacency pair. Computes L1 distance between the
// top-left 15x15 sub-patches (over 3 channels) of two adjacent grid cells
// and scatters the result symmetrically into A.
// Vertical pairs: gw in [0, NV); horizontal pairs: gw in [NV, NV+NH).
// ---------------------------------------------------------------------------
__global__ void edge_kernel(const float* __restrict__ data,
                            float* __restrict__ A) {
    const int NV = BB * (NYC - 1) * NXC;   // 16128
    const int NH = BB * NYC * (NXC - 1);   // 16128
    int gw = (int)(((long long)blockIdx.x * blockDim.x + threadIdx.x) >> 5);
    int lane = threadIdx.x & 31;
    if (gw >= NV + NH) return;

    const int PSQ = PP * PP;               // 225
    const int TOT = CC * PSQ;              // 675

    float s = 0.f;
    if (gw < NV) {
        // vertical pair (b, y, x): cell (y,x) vs cell (y+1,x)
        int b = gw / ((NYC - 1) * NXC);
        int r = gw % ((NYC - 1) * NXC);
        int y = r / NXC, x = r % NXC;
        const float* base = data + (long long)b * CC * HH * WW
                                 + (long long)(y * SCALE) * WW + x * SCALE;
        #pragma unroll 4
        for (int t = lane; t < TOT; t += 32) {
            int c = t / PSQ;
            int rr = t - c * PSQ;
            int i = rr / PP, j = rr - i * PP;
            const float* p = base + (long long)c * HH * WW + i * WW + j;
            s += fabsf(p[SCALE * WW] - p[0]);
        }
        #pragma unroll
        for (int o = 16; o; o >>= 1) s += __shfl_xor_sync(0xffffffffu, s, o);
        if (lane == 0) {
            int hi = y * NXC + x;          // upper cell
            int lo = (y + 1) * NXC + x;    // lower cell
            float* Ab = A + (long long)b * NNODES * NNODES;
            Ab[(long long)lo * NNODES + hi] = s;
            Ab[(long long)hi * NNODES + lo] = s;
        }
    } else {
        // horizontal pair (b, y, x): cell (y,x) vs cell (y,x+1)
        int idx = gw - NV;
        int b = idx / (NYC * (NXC - 1));
        int r = idx % (NYC * (NXC - 1));
        int y = r / (NXC - 1), x = r % (NXC - 1);
        const float* base = data + (long long)b * CC * HH * WW
                                 + (long long)(y * SCALE) * WW + x * SCALE;
        #pragma unroll 4
        for (int t = lane; t < TOT; t += 32) {
            int c = t / PSQ;
            int rr = t - c * PSQ;
            int i = rr / PP, j = rr - i * PP;
            const float* p = base + (long long)c * HH * WW + i * WW + j;
            s += fabsf(p[SCALE] - p[0]);
        }
        #pragma unroll
        for (int o = 16; o; o >>= 1) s += __shfl_xor_sync(0xffffffffu, s, o);
        if (lane == 0) {
            int le = y * NXC + x;
            int ri = le + 1;
            float* Ab = A + (long long)b * NNODES * NNODES;
            Ab[(long long)le * NNODES + ri] = s;
            Ab[(long long)ri * NNODES + le] = s;
        }
    }
}

extern "C" void kernel_launch(void* const* d_in, const int* in_sizes, int n_in,
                              void* d_out, int out_size) {
    const float* data = (const float*)d_in[0];
    float* out = (float*)d_out;

    // out = [A (B*N*N floats), data copy (B*C*H*W floats)]
    long long a_elems = A_ELEMS;
    long long total = (long long)out_size;
    if (total < a_elems) a_elems = total;   // defensive: A-only output
    long long a4 = a_elems >> 2;
    long long total4 = total >> 2;

    // Fill: zeros over A, copy data into tail.
    {
        int threads = 256;
        int blocks = 148 * 24;   // grid-stride, ~19.9M float4s total
        fill_kernel<<<blocks, threads>>>((const float4*)data, (float4*)out,
                                         a4, total4);
    }

    // Edges: one warp per pair; 32256 warps.
    {
        const int NV = BB * (NYC - 1) * NXC;
        const int NH = BB * NYC * (NXC - 1);
        int warps = NV + NH;
        int threads = 256;
        int blocks = (warps * 32 + threads - 1) / threads;
        edge_kernel<<<blocks, threads>>>(data, out);
    }
}

// round 3
// speedup vs baseline: 1.1118x; 1.1118x over previous
#include <cuda_runtime.h>
#include <cstdint>

// Problem constants
#define NXC 64          // nx grid cells
#define NYC 64          // ny grid cells
#define SCALE 16
#define PP 15           // scale-1
#define BB 4
#define CC 3
#define HH 1024
#define WW 1024
#define NNODES 4096     // 64*64
#define CHW (CC*HH*WW)
static const long long A_ELEMS = (long long)BB * NNODES * NNODES;  // 67108864

// ---------------------------------------------------------------------------
// Kernel 1: zero-fill A region of d_out and copy data into the tail.
// Pure float4 streaming writes; grid-stride. Streaming stores (__stcs) keep
// the 268MB of zeros from thrashing L2 (data must stay resident for edge_kernel).
// ---------------------------------------------------------------------------
__global__ void fill_kernel(const float4* __restrict__ src,
                            float4* __restrict__ out,
                            long long a4, long long total4) {
    long long i = (long long)blockIdx.x * blockDim.x + threadIdx.x;
    long long stride = (long long)gridDim.x * blockDim.x;
    const float4 z = make_float4(0.f, 0.f, 0.f, 0.f);
    for (; i < total4; i += stride) {
        if (i < a4) {
            __stcs(&out[i], z);
        } else {
            __stcs(&out[i], src[i - a4]);
        }
    }
}

// ---------------------------------------------------------------------------
// Kernel 2: one warp per adjacency pair.
// Lane mapping: lane = half*16 + j, half in {0,1}, j in 0..15 (j==15 inactive).
// Iterate k=0..7 row-pairs (rows 2k+half) x 3 channels, fully unrolled.
// All addresses are per-channel pointer + compile-time immediate -> minimal ALU.
// ---------------------------------------------------------------------------
__global__ void edge_kernel(const float* __restrict__ data,
                            float* __restrict__ A) {
    const int NV = BB * (NYC - 1) * NXC;   // 16128 vertical pairs
    const int NH = BB * NYC * (NXC - 1);   // 16128 horizontal pairs

    int gw = blockIdx.x * (blockDim.x >> 5) + (threadIdx.x >> 5);
    int lane = threadIdx.x & 31;
    if (gw >= NV + NH) return;

    bool vert = (gw < NV);
    int idx = vert ? gw : (gw - NV);
    // both pair types have 63*64 = 4032 pairs per batch
    int b = idx >> 12;            // idx / 4096? no: 4032 per batch -> can't shift
    b = idx / 4032;
    int r = idx - b * 4032;
    int y, x;
    if (vert) { y = r >> 6; x = r & 63; }          // r / 64, r % 64
    else      { y = r / 63; x = r - y * 63; }

    const float* base = data + (long long)b * CHW
                             + (long long)(y * SCALE) * WW + x * SCALE;
    // neighbor displacement (elements): vertical -> next cell down, horizontal -> next cell right
    int D = vert ? (SCALE * WW) : SCALE;

    int j = lane & 15;
    int half = lane >> 4;
    bool jok = (j < 15);

    // per-lane base: row 'half', column 'j' of the patch
    const float* p0 = base + half * WW + j;

    float s = 0.f;
    #pragma unroll
    for (int c = 0; c < CC; c++) {
        const float* pa = p0 + c * (HH * WW);   // patch element
        const float* pb = pa + D;               // neighbor patch element
        #pragma unroll
        for (int k = 0; k < 8; k++) {
            // row = 2*k + half; valid rows are 0..14
            bool rowok = (k < 7) || (half == 0);
            if (jok && rowok) {
                float a = pa[k * 2 * WW];
                float bdl = pb[k * 2 * WW];
                s += fabsf(a - bdl);
            }
        }
    }

    // warp reduction
    #pragma unroll
    for (int o = 16; o; o >>= 1) s += __shfl_xor_sync(0xffffffffu, s, o);

    if (lane == 0) {
        float* Ab = A + (long long)b * NNODES * NNODES;
        if (vert) {
            int hi = y * NXC + x;          // upper cell
            int lo = hi + NXC;             // lower cell
            Ab[(long long)lo * NNODES + hi] = s;
            Ab[(long long)hi * NNODES + lo] = s;
        } else {
            int le = y * NXC + x;
            int ri = le + 1;
            Ab[(long long)le * NNODES + ri] = s;
            Ab[(long long)ri * NNODES + le] = s;
        }
    }
}

extern "C" void kernel_launch(void* const* d_in, const int* in_sizes, int n_in,
                              void* d_out, int out_size) {
    const float* data = (const float*)d_in[0];
    float* out = (float*)d_out;

    long long a_elems = A_ELEMS;
    long long total = (long long)out_size;
    if (total < a_elems) a_elems = total;   // defensive
    long long a4 = a_elems >> 2;
    long long total4 = total >> 2;

    // Fill: zeros over A, copy data into tail.
    {
        int threads = 256;
        int blocks = 148 * 24;
        fill_kernel<<<blocks, threads>>>((const float4*)data, (float4*)out,
                                         a4, total4);
    }

    // Edges: one warp per pair; 32256 warps, 8 warps/block.
    {
        const int NV = BB * (NYC - 1) * NXC;
        const int NH = BB * NYC * (NXC - 1);
        int warps = NV + NH;
        int threads = 256;
        int blocks = (warps + 7) / 8;
        edge_kernel<<<blocks, threads>>>(data, out);
    }
}

// round 5
// speedup vs baseline: 1.1934x; 1.0734x over previous
#include <cuda_runtime.h>
#include <cstdint>

// Problem constants
#define NXC 64
#define NYC 64
#define SCALE 16
#define PP 15
#define BB 4
#define CC 3
#define HH 1024
#define WW 1024
#define NNODES 4096
#define CHW (CC*HH*WW)
#define NPAIRS_HALF (BB * 63 * 64)      // 16128 vertical == horizontal count
#define NPAIRS (2 * NPAIRS_HALF)        // 32256
static const long long A_ELEMS = (long long)BB * NNODES * NNODES;  // 67108864

#define EDGE_BLOCKS 384
#define FILL_BLOCKS 800
#define TOTAL_BLOCKS (EDGE_BLOCKS + FILL_BLOCKS)
#define THREADS 256

// Edge-value scratch: [0,16128) vertical dv, [16128,32256) horizontal dh
__device__ float g_scratch[NPAIRS];

// ---------------------------------------------------------------------------
// Fused kernel: blocks [0, EDGE_BLOCKS) compute edge L1 sums into g_scratch
// (one warp per pair, grid-stride, float4 loads); remaining blocks stream
// zeros over the A region of out and copy data into the tail.
// ---------------------------------------------------------------------------
__global__ void fused_kernel(const float* __restrict__ data,
                             float4* __restrict__ out,
                             long long a4, long long total4) {
    if (blockIdx.x < EDGE_BLOCKS) {
        // -------- edge compute --------
        int wid = threadIdx.x >> 5;
        int lane = threadIdx.x & 31;
        int warp = blockIdx.x * (THREADS / 32) + wid;
        const int nwarps = EDGE_BLOCKS * (THREADS / 32);

        int c4 = lane & 3;      // float4 column 0..3 (covers cols 4c..4c+3; col 15 masked)
        int rr8 = lane >> 2;    // row within 8-row group, 0..7

        for (int pair = warp; pair < NPAIRS; pair += nwarps) {
            bool vert = pair < NPAIRS_HALF;
            int idx = vert ? pair : pair - NPAIRS_HALF;
            int b = idx / (63 * 64);
            int rm = idx - b * (63 * 64);
            int y, x;
            if (vert) { y = rm >> 6; x = rm & 63; }
            else      { y = rm / 63; x = rm - y * 63; }

            const float* base = data + (long long)b * CHW
                                     + (long long)(y * SCALE) * WW + x * SCALE;
            int D = vert ? (SCALE * WW) : SCALE;

            float s = 0.f;
            #pragma unroll
            for (int c = 0; c < CC; c++) {
                #pragma unroll
                for (int st = 0; st < 2; st++) {
                    int row = st * 8 + rr8;        // rows 0..15; row 15 invalid
                    if (row < PP) {
                        const float* rp = base + c * (HH * WW) + row * WW;
                        float4 a  = __ldg((const float4*)rp + c4);
                        float4 bb = __ldg((const float4*)(rp + D) + c4);
                        s += fabsf(a.x - bb.x) + fabsf(a.y - bb.y) + fabsf(a.z - bb.z);
                        if (c4 < 3) s += fabsf(a.w - bb.w);   // col 15 masked
                    }
                }
            }
            #pragma unroll
            for (int o = 16; o; o >>= 1) s += __shfl_xor_sync(0xffffffffu, s, o);
            if (lane == 0) g_scratch[pair] = s;
        }
    } else {
        // -------- streaming fill / copy --------
        const float4* src = (const float4*)data;
        int fb = blockIdx.x - EDGE_BLOCKS;
        long long i = (long long)fb * THREADS + threadIdx.x;
        const long long stride = (long long)FILL_BLOCKS * THREADS;
        const float4 z = make_float4(0.f, 0.f, 0.f, 0.f);
        for (; i < total4; i += stride) {
            if (i < a4) __stcs(&out[i], z);
            else        __stcs(&out[i], src[i - a4]);
        }
    }
}

// ---------------------------------------------------------------------------
// Scatter: write the 32256 edge values symmetrically into A (after fill).
// ---------------------------------------------------------------------------
__global__ void scatter_kernel(float* __restrict__ A) {
    int i = blockIdx.x * blockDim.x + threadIdx.x;
    if (i >= NPAIRS) return;
    float s = g_scratch[i];
    bool vert = i < NPAIRS_HALF;
    int idx = vert ? i : i - NPAIRS_HALF;
    int b = idx / (63 * 64);
    int rm = idx - b * (63 * 64);
    float* Ab = A + (long long)b * NNODES * NNODES;
    if (vert) {
        int y = rm >> 6, x = rm & 63;
        int hi = y * NXC + x;
        int lo = hi + NXC;
        Ab[(long long)lo * NNODES + hi] = s;
        Ab[(long long)hi * NNODES + lo] = s;
    } else {
        int y = rm / 63, x = rm - y * 63;
        int le = y * NXC + x;
        int ri = le + 1;
        Ab[(long long)le * NNODES + ri] = s;
        Ab[(long long)ri * NNODES + le] = s;
    }
}

extern "C" void kernel_launch(void* const* d_in, const int* in_sizes, int n_in,
                              void* d_out, int out_size) {
    const float* data = (const float*)d_in[0];
    float* out = (float*)d_out;

    long long a_elems = A_ELEMS;
    long long total = (long long)out_size;
    if (total < a_elems) a_elems = total;
    long long a4 = a_elems >> 2;
    long long total4 = total >> 2;

    fused_kernel<<<TOTAL_BLOCKS, THREADS>>>(data, (float4*)out, a4, total4);

    scatter_kernel<<<(NPAIRS + 255) / 256, 256>>>(out);
}